// round 8
// baseline (speedup 1.0000x reference)
#include <cuda_runtime.h>
#include <cstdint>

// ---------------- problem constants ----------------
#define BB   16
#define DD   64
#define HH   768
#define NE   7
#define ROWS (BB*DD)                 // 1024 utterances
#define PAIRS_PER_B (DD*(DD+1)/2)    // 2080
#define NPAIR (BB*PAIRS_PER_B)       // 33280
#define FOLD_TASKS (2*1552)          // 3104
#define W19_FLOATS (19*HH)           // 14592 floats = 58368 bytes
#define W19_F4     (19*192)          // 3648 float4

// ---------------- device scratch (no allocs allowed) ----------------
__device__ float g_Ob[4];             // folded expert bias [e*2+c]
__device__ float g_W19[W19_FLOATS];   // SoA packed weights [m][j]: m 0-6 emo |7-8 G1 |9-10 G2 |11-14 O1 |15-18 O2
__device__ float g_Tail[12*8];        // tail weights for f=768..775: [m][f-768] over the 12 T columns
__device__ float g_T[ROWS*12];        // per-utterance table [G1(2) G2(2) O1(4) O2(4)]
__device__ float g_spk[ROWS];         // speaker ids as float
__device__ unsigned int g_cnt[BB];    // per-batch monotonic sync counters (never reset)

// ================= kernel A: fold experts + pack weights + spk ==============
__global__ void __launch_bounds__(256)
prep_kernel(const void*  __restrict__ spk_raw,
            const float* __restrict__ emo_w,
            const float* __restrict__ gate_w,
            const float* __restrict__ w1,
            const float* __restrict__ b1,
            const float* __restrict__ w2,
            const float* __restrict__ b2) {
    const int gw   = (blockIdx.x * blockDim.x + threadIdx.x) >> 5;
    const int lane = threadIdx.x & 31;

    if (gw < FOLD_TASKS) {
        const int e = gw / 1552, j = gw - e * 1552;
        const float4* a4  = (const float4*)(w1 + ((size_t)(e * 1552 + j)) * 256);
        const float4* wb4 = (const float4*)(w2 + e * 512);
        float4 x0 = a4[lane];
        float4 x1 = a4[lane + 32];
        float4 p0 = wb4[2 * lane];
        float4 p1 = wb4[2 * lane + 1];
        float4 p2 = wb4[64 + 2 * lane];
        float4 p3 = wb4[65 + 2 * lane];
        float a0 = x0.x*p0.x + x0.y*p0.z + x0.z*p1.x + x0.w*p1.z
                 + x1.x*p2.x + x1.y*p2.z + x1.z*p3.x + x1.w*p3.z;
        float a1 = x0.x*p0.y + x0.y*p0.w + x0.z*p1.y + x0.w*p1.w
                 + x1.x*p2.y + x1.y*p2.w + x1.z*p3.y + x1.w*p3.w;
        #pragma unroll
        for (int off = 16; off; off >>= 1) {
            a0 += __shfl_down_sync(0xffffffffu, a0, off);
            a1 += __shfl_down_sync(0xffffffffu, a1, off);
        }
        if (lane == 0) {
            if (j < HH) {                          // first-half feature -> O1 (m = 11+e*2+c)
                g_W19[(11 + e * 2) * HH + j] = a0;
                g_W19[(12 + e * 2) * HH + j] = a1;
            } else if (j < 776) {                  // tail O1 feature: Tail m = 4+e*2+c
                g_Tail[(4 + e * 2) * 8 + (j - HH)] = a0;
                g_Tail[(5 + e * 2) * 8 + (j - HH)] = a1;
            } else if (j < 776 + HH) {             // second-half feature -> O2 (m = 15+e*2+c)
                int jj = j - 776;
                g_W19[(15 + e * 2) * HH + jj] = a0;
                g_W19[(16 + e * 2) * HH + jj] = a1;
            } else {                               // tail O2 feature: Tail m = 8+e*2+c
                g_Tail[(8 + e * 2) * 8 + (j - 776 - HH)] = a0;
                g_Tail[(9 + e * 2) * 8 + (j - 776 - HH)] = a1;
            }
        }
    } else if (gw < FOLD_TASKS + 4) {
        const int idx = gw - FOLD_TASKS;          // 0..3
        const int e = idx >> 1, c = idx & 1;
        float s = 0.f;
        for (int k = lane; k < 256; k += 32)
            s += b1[e * 256 + k] * w2[e * 512 + k * 2 + c];
        #pragma unroll
        for (int off = 16; off; off >>= 1)
            s += __shfl_down_sync(0xffffffffu, s, off);
        if (lane == 0) g_Ob[idx] = s + b2[e * 2 + c];
    } else if (gw == FOLD_TASKS + 4) {
        // speaker_ids stored int64 or int32 (values in {0,1}).
        // int64: odd 32-bit words of first 1024 words are all zero.
        const unsigned int* u = (const unsigned int*)spk_raw;
        unsigned nz = 0;
        for (int i = lane; i < ROWS; i += 32) nz |= u[2 * i + 1];
        unsigned any = __ballot_sync(0xffffffffu, nz != 0u);
        const bool w64 = (any == 0u);
        for (int i = lane; i < ROWS; i += 32)
            g_spk[i] = (float)(w64 ? u[2 * i] : u[i]);
    } else if (gw < FOLD_TASKS + 16) {
        // pack emo (5376) + G1 (1536) + G2 (1536) + gate tail (32) = 8480 elems
        const int pid = gw - (FOLD_TASKS + 5);    // 0..10
        for (int idx = pid * 32 + lane; idx < 8480; idx += 11 * 32) {
            if (idx < 5376) {
                int c = idx / HH, j = idx - c * HH;       // m = c
                g_W19[c * HH + j] = emo_w[j * 7 + c];
            } else if (idx < 5376 + 1536) {
                int q = idx - 5376;
                int c = q / HH, j = q - c * HH;           // m = 7+c
                g_W19[(7 + c) * HH + j] = gate_w[j * 2 + c];
            } else if (idx < 5376 + 3072) {
                int q = idx - 5376 - 1536;
                int c = q / HH, j = q - c * HH;           // m = 9+c
                g_W19[(9 + c) * HH + j] = gate_w[(776 + j) * 2 + c];
            } else {
                int q = idx - 5376 - 3072;                // 0..31
                int m = q >> 3, f8 = q & 7;
                int f = HH + f8;
                float v = (m < 2) ? gate_w[f * 2 + m]
                                  : gate_w[(776 + f) * 2 + (m - 2)];
                g_Tail[m * 8 + f8] = v;
            }
        }
    }
}

// ================= kernel B: smem-weight table + pairs ======================
// grid 128 x 256: block = 8 consecutive rows; stages all 58KB of g_W19 into
// dynamic smem once, then warp = (row-pair rp = warp>>1, j-half jh = warp&1):
// rows base+2rp, base+2rp+1 over float4 indices [jh*96,(jh+1)*96).
// x is prefetched to registers BEFORE staging so DRAM overlaps L2 staging.
// Finalize: warps 0-7, one row each. Per-batch sync: 8 blocks/counter.
// Pair phase: 260 pairs per block.
__global__ void __launch_bounds__(256)
solve_kernel(const float* __restrict__ pooled,
             const float* __restrict__ emo_b,
             const float* __restrict__ gate_b,
             float* __restrict__ out_emo,     // [1024*7]
             float* __restrict__ out_cause) { // [33280*2]
    extern __shared__ float sW[];             // W19_FLOATS floats (58368 B)
    __shared__ float sp[8][2][20];            // [row_in_block][jhalf][m]

    const int tid  = threadIdx.x;
    const int lane = tid & 31;
    const int warp = tid >> 5;
    const int base = blockIdx.x * 8;          // first row of this block
    const int b    = blockIdx.x >> 3;         // batch
    const int s    = blockIdx.x & 7;          // pair slice

    const int rp = warp >> 1;                 // row-pair 0..3
    const int jh = warp & 1;                  // j-half 0..1
    const int i0 = base + rp * 2;
    const int i1 = i0 + 1;

    // ---- prefetch x (DRAM) into registers ----
    const float4* r0 = (const float4*)(pooled + (size_t)i0 * HH);
    const float4* r1 = (const float4*)(pooled + (size_t)i1 * HH);
    float4 x0[3], x1[3];
    #pragma unroll
    for (int u = 0; u < 3; u++) {
        const int k = jh * 96 + u * 32 + lane;
        x0[u] = r0[k];
        x1[u] = r1[k];
    }

    // ---- stage weights (L2) into smem ----
    {
        const float4* gW4 = (const float4*)g_W19;
        float4* sW4 = (float4*)sW;
        for (int t = tid; t < W19_F4; t += 256)
            sW4[t] = gW4[t];
    }
    __syncthreads();

    // ---- accumulate from smem ----
    float aA[19], aB[19];
    #pragma unroll
    for (int m = 0; m < 19; m++) { aA[m] = 0.f; aB[m] = 0.f; }

    #pragma unroll
    for (int u = 0; u < 3; u++) {
        const int k = jh * 96 + u * 32 + lane;
        const float4 v0 = x0[u];
        const float4 v1 = x1[u];
        #pragma unroll
        for (int m = 0; m < 19; m++) {
            float4 w = ((const float4*)sW)[m * 192 + k];
            aA[m] += v0.x*w.x + v0.y*w.y + v0.z*w.z + v0.w*w.w;
            aB[m] += v1.x*w.x + v1.y*w.y + v1.z*w.z + v1.w*w.w;
        }
    }

    #pragma unroll
    for (int off = 16; off; off >>= 1) {
        #pragma unroll
        for (int m = 0; m < 19; m++) {
            aA[m] += __shfl_down_sync(0xffffffffu, aA[m], off);
            aB[m] += __shfl_down_sync(0xffffffffu, aB[m], off);
        }
    }
    if (lane == 0) {
        #pragma unroll
        for (int m = 0; m < 19; m++) {
            sp[rp * 2 + 0][jh][m] = aA[m];
            sp[rp * 2 + 1][jh][m] = aB[m];
        }
    }
    __syncthreads();

    // ---- finalize: warps 0-7, one row each, lanes = m ----
    {
        const int row = warp;                 // 0..7
        const int i = base + row;
        float sacc = 0.f;
        if (lane < 19)
            sacc = sp[row][0][lane] + sp[row][1][lane];
        float ep = (lane < 7) ? sacc + emo_b[lane] : 0.f;

        // convergent broadcasts (all 32 lanes execute the same shfls)
        float epv[7];
        #pragma unroll
        for (int f8 = 0; f8 < 7; f8++)
            epv[f8] = __shfl_sync(0xffffffffu, ep, f8);

        if (lane < 7)
            out_emo[(size_t)i * 7 + lane] = ep;
        else if (lane < 19) {
            const int m = lane - 7;           // T column 0..11
            float v = sacc;
            #pragma unroll
            for (int f8 = 0; f8 < 7; f8++)
                v += epv[f8] * g_Tail[m * 8 + f8];
            v += g_spk[i] * g_Tail[m * 8 + 7];
            g_T[i * 12 + m] = v;
        }
    }

    // ---- per-batch sync (monotonic ticket; 8 blocks per counter) ----
    __syncthreads();
    if (tid == 0) {
        __threadfence();
        unsigned t = atomicAdd(&g_cnt[b], 1u) + 1u;
        unsigned round_end = ((t + 7u) / 8u) * 8u;
        volatile unsigned int* c = &g_cnt[b];
        while (*c < round_end) { __nanosleep(32); }
        __threadfence();
    }
    __syncthreads();

    // ---- pair phase: 260 pairs per block ----
    const float gb0 = gate_b[0];
    const float gb1 = gate_b[1];
    const float ob0 = g_Ob[0], ob1 = g_Ob[1], ob2 = g_Ob[2], ob3 = g_Ob[3];
    const float* Tb = g_T + b * DD * 12;

    for (int ql = tid; ql < 260; ql += 256) {
        int q = s * 260 + ql;                 // 0..2079 within batch
        int end = (int)((sqrtf(8.f * (float)q + 1.f) - 1.f) * 0.5f);
        while ((end + 1) * (end + 2) / 2 <= q) end++;
        while (end * (end + 1) / 2 > q) end--;
        int t = q - end * (end + 1) / 2;

        const float* Tt = Tb + t   * 12;
        const float* Te = Tb + end * 12;

        float g0 = Tt[0] + Te[2] + gb0;
        float g1 = Tt[1] + Te[3] + gb1;

        float o00 = Tt[4] + Te[8]  + ob0;
        float o01 = Tt[5] + Te[9]  + ob1;
        float o10 = Tt[6] + Te[10] + ob2;
        float o11 = Tt[7] + Te[11] + ob3;

        size_t p = (size_t)b * PAIRS_PER_B + q;
        out_cause[p * 2 + 0] = g0 * o00 + g1 * o10;
        out_cause[p * 2 + 1] = g0 * o01 + g1 * o11;
    }
}

// ---------------- launch ----------------
extern "C" void kernel_launch(void* const* d_in, const int* in_sizes, int n_in,
                              void* d_out, int out_size) {
    const float* pooled  = (const float*)d_in[0];
    const void*  spk     = d_in[1];
    const float* emo_w   = (const float*)d_in[2];
    const float* emo_b   = (const float*)d_in[3];
    const float* gate_w  = (const float*)d_in[4];
    const float* gate_b  = (const float*)d_in[5];
    const float* exp_w1  = (const float*)d_in[6];
    const float* exp_b1  = (const float*)d_in[7];
    const float* exp_w2  = (const float*)d_in[8];
    const float* exp_b2  = (const float*)d_in[9];
    float* out = (float*)d_out;

    // opt-in >48KB dynamic smem (host attr set, not an allocation; capture-safe)
    cudaFuncSetAttribute(solve_kernel,
                         cudaFuncAttributeMaxDynamicSharedMemorySize,
                         W19_FLOATS * sizeof(float));

    prep_kernel<<<390, 256>>>(spk, emo_w, gate_w, exp_w1, exp_b1, exp_w2, exp_b2);
    solve_kernel<<<128, 256, W19_FLOATS * sizeof(float)>>>(
        pooled, emo_b, gate_b, out, out + ROWS * NE);
}

// round 9
// speedup vs baseline: 1.2226x; 1.2226x over previous
#include <cuda_runtime.h>
#include <cstdint>

// ---------------- problem constants ----------------
#define BB   16
#define DD   64
#define HH   768
#define NE   7
#define ROWS (BB*DD)                 // 1024 utterances
#define PAIRS_PER_B (DD*(DD+1)/2)    // 2080
#define NPAIR (BB*PAIRS_PER_B)       // 33280
#define FOLD_TASKS (2*1552)          // 3104

// ---------------- device scratch (no allocs allowed) ----------------
__device__ float g_Ob[4];             // folded expert bias [e*2+c]
__device__ float g_W19[19*HH];        // SoA packed weights [m][j]: m 0-6 emo |7-8 G1 |9-10 G2 |11-14 O1 |15-18 O2
__device__ float g_Tail[12*8];        // tail weights for f=768..775: [m][f-768] over the 12 T columns
__device__ float g_T[ROWS*12];        // per-utterance table [G1(2) G2(2) O1(4) O2(4)]
__device__ float g_spk[ROWS];         // speaker ids as float
__device__ unsigned short g_pairidx[PAIRS_PER_B]; // packed (end<<8)|t per in-batch pair q
__device__ unsigned int g_cnt[BB];    // per-batch monotonic sync counters (never reset)

// ================= kernel A: fold experts + pack weights + spk + pair LUT ===
// grid 400 x 256 = 3200 warps:
//   0..3103     : fold row (e,j) -> g_W19 / g_Tail
//   3104..3107  : Ob
//   3108        : speaker convert
//   3109..3119  : pack emo/gate into g_W19 SoA + gate tail
//   3120..3184  : pair index LUT (65 warps x 32 = 2080)
__global__ void __launch_bounds__(256)
prep_kernel(const void*  __restrict__ spk_raw,
            const float* __restrict__ emo_w,
            const float* __restrict__ gate_w,
            const float* __restrict__ w1,
            const float* __restrict__ b1,
            const float* __restrict__ w2,
            const float* __restrict__ b2) {
    const int gw   = (blockIdx.x * blockDim.x + threadIdx.x) >> 5;
    const int lane = threadIdx.x & 31;

    if (gw < FOLD_TASKS) {
        const int e = gw / 1552, j = gw - e * 1552;
        const float4* a4  = (const float4*)(w1 + ((size_t)(e * 1552 + j)) * 256);
        const float4* wb4 = (const float4*)(w2 + e * 512);
        float4 x0 = a4[lane];
        float4 x1 = a4[lane + 32];
        float4 p0 = wb4[2 * lane];
        float4 p1 = wb4[2 * lane + 1];
        float4 p2 = wb4[64 + 2 * lane];
        float4 p3 = wb4[65 + 2 * lane];
        float a0 = x0.x*p0.x + x0.y*p0.z + x0.z*p1.x + x0.w*p1.z
                 + x1.x*p2.x + x1.y*p2.z + x1.z*p3.x + x1.w*p3.z;
        float a1 = x0.x*p0.y + x0.y*p0.w + x0.z*p1.y + x0.w*p1.w
                 + x1.x*p2.y + x1.y*p2.w + x1.z*p3.y + x1.w*p3.w;
        #pragma unroll
        for (int off = 16; off; off >>= 1) {
            a0 += __shfl_down_sync(0xffffffffu, a0, off);
            a1 += __shfl_down_sync(0xffffffffu, a1, off);
        }
        if (lane == 0) {
            if (j < HH) {                          // first-half feature -> O1 (m = 11+e*2+c)
                g_W19[(11 + e * 2) * HH + j] = a0;
                g_W19[(12 + e * 2) * HH + j] = a1;
            } else if (j < 776) {                  // tail O1 feature: Tail m = 4+e*2+c
                g_Tail[(4 + e * 2) * 8 + (j - HH)] = a0;
                g_Tail[(5 + e * 2) * 8 + (j - HH)] = a1;
            } else if (j < 776 + HH) {             // second-half feature -> O2 (m = 15+e*2+c)
                int jj = j - 776;
                g_W19[(15 + e * 2) * HH + jj] = a0;
                g_W19[(16 + e * 2) * HH + jj] = a1;
            } else {                               // tail O2 feature: Tail m = 8+e*2+c
                g_Tail[(8 + e * 2) * 8 + (j - 776 - HH)] = a0;
                g_Tail[(9 + e * 2) * 8 + (j - 776 - HH)] = a1;
            }
        }
    } else if (gw < FOLD_TASKS + 4) {
        const int idx = gw - FOLD_TASKS;          // 0..3
        const int e = idx >> 1, c = idx & 1;
        float s = 0.f;
        for (int k = lane; k < 256; k += 32)
            s += b1[e * 256 + k] * w2[e * 512 + k * 2 + c];
        #pragma unroll
        for (int off = 16; off; off >>= 1)
            s += __shfl_down_sync(0xffffffffu, s, off);
        if (lane == 0) g_Ob[idx] = s + b2[e * 2 + c];
    } else if (gw == FOLD_TASKS + 4) {
        // speaker_ids stored int64 or int32 (values in {0,1}).
        // int64: odd 32-bit words of first 1024 words are all zero.
        const unsigned int* u = (const unsigned int*)spk_raw;
        unsigned nz = 0;
        for (int i = lane; i < ROWS; i += 32) nz |= u[2 * i + 1];
        unsigned any = __ballot_sync(0xffffffffu, nz != 0u);
        const bool w64 = (any == 0u);
        for (int i = lane; i < ROWS; i += 32)
            g_spk[i] = (float)(w64 ? u[2 * i] : u[i]);
    } else if (gw < FOLD_TASKS + 16) {
        // pack emo (5376) + G1 (1536) + G2 (1536) + gate tail (32) = 8480 elems
        const int pid = gw - (FOLD_TASKS + 5);    // 0..10
        for (int idx = pid * 32 + lane; idx < 8480; idx += 11 * 32) {
            if (idx < 5376) {
                int c = idx / HH, j = idx - c * HH;       // m = c
                g_W19[c * HH + j] = emo_w[j * 7 + c];
            } else if (idx < 5376 + 1536) {
                int q = idx - 5376;
                int c = q / HH, j = q - c * HH;           // m = 7+c
                g_W19[(7 + c) * HH + j] = gate_w[j * 2 + c];
            } else if (idx < 5376 + 3072) {
                int q = idx - 5376 - 1536;
                int c = q / HH, j = q - c * HH;           // m = 9+c
                g_W19[(9 + c) * HH + j] = gate_w[(776 + j) * 2 + c];
            } else {
                int q = idx - 5376 - 3072;                // 0..31
                int m = q >> 3, f8 = q & 7;
                int f = HH + f8;
                float v = (m < 2) ? gate_w[f * 2 + m]
                                  : gate_w[(776 + f) * 2 + (m - 2)];
                g_Tail[m * 8 + f8] = v;
            }
        }
    } else if (gw < FOLD_TASKS + 16 + 65) {
        // pair index LUT: q -> (end, t), end-major tril order
        const int q = (gw - (FOLD_TASKS + 16)) * 32 + lane;
        if (q < PAIRS_PER_B) {
            int end = (int)((sqrtf(8.f * (float)q + 1.f) - 1.f) * 0.5f);
            while ((end + 1) * (end + 2) / 2 <= q) end++;
            while (end * (end + 1) / 2 > q) end--;
            int t = q - end * (end + 1) / 2;
            g_pairidx[q] = (unsigned short)((end << 8) | t);
        }
    }
}

// ================= kernel B: table (1 row x 2 j-chunks per warp) + pairs ====
// grid 256 x 256, 2 blocks/SM: block = 4 consecutive rows.
// Warp w: row = base + (w>>1), j-chunk jh = w&1 (float4 [jh*96,(jh+1)*96),
// 3 positions per lane). Finalize: warps 0-3, one row each.
// Per-batch monotonic sync (16 blocks/counter), then 130 pairs via LUT.
__global__ void __launch_bounds__(256, 2)
solve_kernel(const float* __restrict__ pooled,
             const float* __restrict__ emo_b,
             const float* __restrict__ gate_b,
             float* __restrict__ out_emo,     // [1024*7]
             float* __restrict__ out_cause) { // [33280*2]
    const int tid  = threadIdx.x;
    const int lane = tid & 31;
    const int warp = tid >> 5;
    const int base = blockIdx.x * 4;              // first row of this block
    const int b    = blockIdx.x >> 4;             // batch
    const int s    = blockIdx.x & 15;             // pair slice

    __shared__ float sp[4][2][20];                // [row_in_block][jchunk][m]

    // ---- accumulate: warp = (row, j-chunk) ----
    {
        const int row = warp >> 1;                // 0..3
        const int jh  = warp & 1;                 // 0..1
        const int i = base + row;
        const float4* r = (const float4*)(pooled + (size_t)i * HH);

        // prefetch x (DRAM) with full MLP
        float4 x[3];
        #pragma unroll
        for (int u = 0; u < 3; u++)
            x[u] = r[jh * 96 + u * 32 + lane];

        float acc[19];
        #pragma unroll
        for (int m = 0; m < 19; m++) acc[m] = 0.f;

        #pragma unroll
        for (int u = 0; u < 3; u++) {
            const int k = jh * 96 + u * 32 + lane;
            const float4 v = x[u];
            #pragma unroll
            for (int m = 0; m < 19; m++) {
                float4 w = __ldg((const float4*)(g_W19 + m * HH) + k);
                acc[m] += v.x*w.x + v.y*w.y + v.z*w.z + v.w*w.w;
            }
        }

        #pragma unroll
        for (int off = 16; off; off >>= 1) {
            #pragma unroll
            for (int m = 0; m < 19; m++)
                acc[m] += __shfl_down_sync(0xffffffffu, acc[m], off);
        }
        if (lane == 0) {
            #pragma unroll
            for (int m = 0; m < 19; m++)
                sp[row][jh][m] = acc[m];
        }
    }
    __syncthreads();

    // ---- finalize: warps 0-3, one row each, lanes = m ----
    if (warp < 4) {
        const int row = warp;
        const int i = base + row;
        float sacc = 0.f;
        if (lane < 19)
            sacc = sp[row][0][lane] + sp[row][1][lane];
        float ep = (lane < 7) ? sacc + emo_b[lane] : 0.f;

        // convergent broadcasts (all 32 lanes execute the same shfls)
        float epv[7];
        #pragma unroll
        for (int f8 = 0; f8 < 7; f8++)
            epv[f8] = __shfl_sync(0xffffffffu, ep, f8);

        if (lane < 7)
            out_emo[(size_t)i * 7 + lane] = ep;
        else if (lane < 19) {
            const int m = lane - 7;               // T column 0..11
            float v = sacc;
            #pragma unroll
            for (int f8 = 0; f8 < 7; f8++)
                v += epv[f8] * g_Tail[m * 8 + f8];
            v += g_spk[i] * g_Tail[m * 8 + 7];
            g_T[i * 12 + m] = v;
        }
    }

    // ---- per-batch sync (monotonic ticket; 16 blocks per counter) ----
    __syncthreads();
    if (tid == 0) {
        __threadfence();
        unsigned t = atomicAdd(&g_cnt[b], 1u) + 1u;
        unsigned round_end = ((t + 15u) / 16u) * 16u;
        volatile unsigned int* c = &g_cnt[b];
        while (*c < round_end) { __nanosleep(32); }
        __threadfence();
    }
    __syncthreads();

    // ---- pair phase: 130 pairs per block via LUT ----
    if (tid < 130) {
        const float gb0 = gate_b[0];
        const float gb1 = gate_b[1];
        const float ob0 = g_Ob[0], ob1 = g_Ob[1], ob2 = g_Ob[2], ob3 = g_Ob[3];
        const float* Tb = g_T + b * DD * 12;

        const int q = s * 130 + tid;              // 0..2079 within batch
        const unsigned pe = g_pairidx[q];
        const int end = pe >> 8;
        const int t   = pe & 255;

        const float* Tt = Tb + t   * 12;
        const float* Te = Tb + end * 12;

        float g0 = Tt[0] + Te[2] + gb0;
        float g1 = Tt[1] + Te[3] + gb1;

        float o00 = Tt[4] + Te[8]  + ob0;
        float o01 = Tt[5] + Te[9]  + ob1;
        float o10 = Tt[6] + Te[10] + ob2;
        float o11 = Tt[7] + Te[11] + ob3;

        size_t p = (size_t)b * PAIRS_PER_B + q;
        out_cause[p * 2 + 0] = g0 * o00 + g1 * o10;
        out_cause[p * 2 + 1] = g0 * o01 + g1 * o11;
    }
}

// ---------------- launch ----------------
extern "C" void kernel_launch(void* const* d_in, const int* in_sizes, int n_in,
                              void* d_out, int out_size) {
    const float* pooled  = (const float*)d_in[0];
    const void*  spk     = d_in[1];
    const float* emo_w   = (const float*)d_in[2];
    const float* emo_b   = (const float*)d_in[3];
    const float* gate_w  = (const float*)d_in[4];
    const float* gate_b  = (const float*)d_in[5];
    const float* exp_w1  = (const float*)d_in[6];
    const float* exp_b1  = (const float*)d_in[7];
    const float* exp_w2  = (const float*)d_in[8];
    const float* exp_b2  = (const float*)d_in[9];
    float* out = (float*)d_out;

    prep_kernel<<<400, 256>>>(spk, emo_w, gate_w, exp_w1, exp_b1, exp_w2, exp_b2);
    solve_kernel<<<256, 256>>>(pooled, emo_b, gate_b, out, out + ROWS * NE);
}